// round 4
// baseline (speedup 1.0000x reference)
#include <cuda_runtime.h>

// ---------------------------------------------------------------------------
// Talking-heads MHSA, B=2 P=2048 H=8 DF=32, fp32.
//   k1: QKV = x @ Wqkv^T -> g_q (pre-scaled), g_k, g_v   [B,H,P,32]
//   k2: fused attention, 512 thr/CTA, 2 split-K copies w/ named barriers
//   k3: out = ctxt @ Wproj^T
// ---------------------------------------------------------------------------

#define DEV_INLINE __device__ __forceinline__

struct U64F2 { union { unsigned long long u; float2 f; }; };

DEV_INLINE U64F2 f2fma(U64F2 a, U64F2 b, U64F2 c) {
    U64F2 d;
    asm("fma.rn.f32x2 %0, %1, %2, %3;" : "=l"(d.u) : "l"(a.u), "l"(b.u), "l"(c.u));
    return d;
}
DEV_INLINE U64F2 f2mul(U64F2 a, U64F2 b) {
    U64F2 d;
    asm("mul.rn.f32x2 %0, %1, %2;" : "=l"(d.u) : "l"(a.u), "l"(b.u));
    return d;
}
DEV_INLINE U64F2 pk2(float v) {
    U64F2 d;
    asm("mov.b64 %0, {%1, %1};" : "=l"(d.u) : "f"(v));
    return d;
}

constexpr int Bc = 2, Pc = 2048, Hc = 8, DFc = 32;
constexpr float QSCALE = 0.17677669529663687f;  // 1/sqrt(32)

__device__ float g_q[Bc * Hc * Pc * DFc];
__device__ float g_k[Bc * Hc * Pc * DFc];
__device__ float g_v[Bc * Hc * Pc * DFc];
__device__ float g_ctxt[Bc * Pc * Hc * DFc];

// ---------------------------------------------------------------------------
// GEMM: C[M,N] = A[M,K] @ Bw[N,K]^T (unchanged from R2)
// ---------------------------------------------------------------------------
template <int EPI>
__global__ __launch_bounds__(256) void gemm_nt(const float* __restrict__ A,
                                               const float* __restrict__ Bw,
                                               float* __restrict__ C,
                                               int M, int N, int K) {
    __shared__ __align__(16) float As[64][68];
    __shared__ __align__(16) float Bs[64][68];

    const int tid = threadIdx.x;
    const int tx = tid & 15, ty = tid >> 4;
    const int m0 = blockIdx.x << 6, n0 = blockIdx.y << 6;
    const int bn = tid & 63;
    const int bk = (tid >> 6) << 4;

    U64F2 acc[4][2];
#pragma unroll
    for (int i = 0; i < 4; i++) {
        acc[i][0].f = make_float2(0.f, 0.f);
        acc[i][1].f = make_float2(0.f, 0.f);
    }

    for (int kc = 0; kc < K; kc += 64) {
#pragma unroll
        for (int i = 0; i < 4; i++) {
            int v = tid + (i << 8);
            int r = v >> 4, k4 = v & 15;
            *(float4*)&As[r][k4 << 2] =
                *(const float4*)&A[(size_t)(m0 + r) * K + kc + (k4 << 2)];
        }
#pragma unroll
        for (int c4 = 0; c4 < 4; c4++) {
            float4 bv =
                *(const float4*)&Bw[(size_t)(n0 + bn) * K + kc + bk + (c4 << 2)];
            Bs[bk + (c4 << 2) + 0][bn] = bv.x;
            Bs[bk + (c4 << 2) + 1][bn] = bv.y;
            Bs[bk + (c4 << 2) + 2][bn] = bv.z;
            Bs[bk + (c4 << 2) + 3][bn] = bv.w;
        }
        __syncthreads();
#pragma unroll 8
        for (int kk = 0; kk < 64; kk++) {
            float4 b01 = *(const float4*)&Bs[kk][tx << 2];
            U64F2 b0, b1;
            b0.f = make_float2(b01.x, b01.y);
            b1.f = make_float2(b01.z, b01.w);
#pragma unroll
            for (int i = 0; i < 4; i++) {
                U64F2 a2 = pk2(As[(ty << 2) + i][kk]);
                acc[i][0] = f2fma(a2, b0, acc[i][0]);
                acc[i][1] = f2fma(a2, b1, acc[i][1]);
            }
        }
        __syncthreads();
    }

    if (EPI == 0) {
#pragma unroll
        for (int i = 0; i < 4; i++) {
            float4 vout;
            vout.x = acc[i][0].f.x; vout.y = acc[i][0].f.y;
            vout.z = acc[i][1].f.x; vout.w = acc[i][1].f.y;
            *(float4*)&C[(size_t)(m0 + (ty << 2) + i) * N + n0 + (tx << 2)] = vout;
        }
    } else {
#pragma unroll
        for (int i = 0; i < 4; i++) {
            float vals[4] = {acc[i][0].f.x, acc[i][0].f.y, acc[i][1].f.x, acc[i][1].f.y};
            int r = m0 + (ty << 2) + i;
            int bb = r >> 11, p = r & 2047;
#pragma unroll
            for (int j = 0; j < 4; j++) {
                int c = n0 + (tx << 2) + j;
                int sgrp = c >> 8;
                int h = (c >> 5) & 7, d = c & 31;
                int idx = ((bb * Hc + h) * Pc + p) * DFc + d;
                if (sgrp == 0)      g_q[idx] = vals[j] * QSCALE;
                else if (sgrp == 1) g_k[idx] = vals[j];
                else                g_v[idx] = vals[j];
            }
        }
    }
}

// ---------------------------------------------------------------------------
// Fused talking-heads attention. 512 threads; warps 0-7 = copy 0 (even key
// tiles), warps 8-15 = copy 1 (odd key tiles). Per-copy named barriers.
// Within a copy: warp = head h (also output head g), lane = query row.
// ---------------------------------------------------------------------------
struct AttnSmem {
    float Ks[2][8][32][36];  // K tile (stride 36); reused as Bs[8][32][33] bias/scores
    float Vs[2][8][32][32];
    float SP[2][8][32][32];  // raw scores, layout [h][kq][p]
    float ml1[8][32][2];     // copy 1 (m,l) for the final merge
};

DEV_INLINE void barC(int s) {
    asm volatile("bar.sync %0, %1;" :: "r"(s + 1), "r"(256) : "memory");
}

__global__ __launch_bounds__(512, 1) void attn_fused(const float* __restrict__ bias,
                                                     const float* __restrict__ wtalk) {
    extern __shared__ char smem_raw[];
    AttnSmem& sm = *reinterpret_cast<AttnSmem*>(smem_raw);

    const int b = blockIdx.x & 1;
    const int p0 = (blockIdx.x >> 1) * 32;
    const int tid = threadIdx.x;
    const int warp = tid >> 5, lane = tid & 31;
    const int s = warp >> 3;      // copy index
    const int h = warp & 7;       // head (= output head g)
    const int tloc = tid & 255;   // thread id within copy
    const int srow = tloc >> 3, sd4 = tloc & 7;  // staging row / float4-chunk

    float wv[8];
#pragma unroll
    for (int hh = 0; hh < 8; hh++) wv[hh] = wtalk[h * 8 + hh];

    // Q rows (head h, query p0+lane), pre-scaled (identical in both copies).
    U64F2 q[16];
    {
        const float4* qp =
            (const float4*)&g_q[((size_t)(b * Hc + h) * Pc + p0 + lane) * DFc];
#pragma unroll
        for (int i = 0; i < 8; i++) {
            float4 v = qp[i];
            q[2 * i].f     = make_float2(v.x, v.y);
            q[2 * i + 1].f = make_float2(v.z, v.w);
        }
    }
    U64F2 o[16];
#pragma unroll
    for (int i = 0; i < 16; i++) o[i].f = make_float2(0.f, 0.f);
    float m_run = -1e30f, l_run = 0.f;

    const float4* kb4 = (const float4*)&g_k[(size_t)b * Hc * Pc * DFc];
    const float4* vb4 = (const float4*)&g_v[(size_t)b * Hc * Pc * DFc];
    const float4* bias4 = (const float4*)bias;

    float* bs = &sm.Ks[s][0][0][0];  // bias/mixed-score overlay, stride 33

    // prefetch first bias tile: chunk i -> (head i, row srow, d4 sd4)
    float4 breg[8];
    {
        const int kq0 = s * 32;
#pragma unroll
        for (int i = 0; i < 8; i++)
            breg[i] = bias4[(size_t)(i * Pc + p0 + srow) * (Pc / 4) + (kq0 >> 2) + sd4];
    }

    for (int tt = 0; tt < 32; tt++) {
        const int kq0 = (tt * 2 + s) * 32;

        // ---- stage K (stride 36), V (stride 32) ----
#pragma unroll
        for (int i = 0; i < 8; i++) {
            float4 kv = kb4[(size_t)(i * Pc + kq0 + srow) * 8 + sd4];
            float4 vv = vb4[(size_t)(i * Pc + kq0 + srow) * 8 + sd4];
            *(float4*)&sm.Ks[s][i][srow][sd4 << 2] = kv;
            *(float4*)&sm.Vs[s][i][srow][sd4 << 2] = vv;
        }
        barC(s);

        // ---- phase 1: S[h][kq][p=lane] = q . k ----
        {
            const float4* kbase = (const float4*)&sm.Ks[s][h][0][0];
#pragma unroll 4
            for (int kq = 0; kq < 32; kq++) {
                const float4* kp = kbase + kq * 9;
                U64F2 a0, a1, a2, a3;
                a0.f = make_float2(0.f, 0.f); a1.f = a0.f; a2.f = a0.f; a3.f = a0.f;
#pragma unroll
                for (int j = 0; j < 8; j += 2) {
                    float4 k0 = kp[j], k1 = kp[j + 1];
                    U64F2 t0, t1, t2, t3;
                    t0.f = make_float2(k0.x, k0.y);
                    t1.f = make_float2(k0.z, k0.w);
                    t2.f = make_float2(k1.x, k1.y);
                    t3.f = make_float2(k1.z, k1.w);
                    a0 = f2fma(q[2 * j],     t0, a0);
                    a1 = f2fma(q[2 * j + 1], t1, a1);
                    a2 = f2fma(q[2 * j + 2], t2, a2);
                    a3 = f2fma(q[2 * j + 3], t3, a3);
                }
                sm.SP[s][h][kq][lane] =
                    (a0.f.x + a0.f.y) + (a1.f.x + a1.f.y) +
                    ((a2.f.x + a2.f.y) + (a3.f.x + a3.f.y));
            }
        }
        barC(s);  // K tile now dead -> overlay bias

        // ---- dump prefetched bias into overlay, prefetch next ----
#pragma unroll
        for (int i = 0; i < 8; i++) {
            float* dst = &bs[(i * 32 + srow) * 33 + (sd4 << 2)];
            dst[0] = breg[i].x; dst[1] = breg[i].y;
            dst[2] = breg[i].z; dst[3] = breg[i].w;
        }
        if (tt != 31) {
            const int kqn = kq0 + 64;
#pragma unroll
            for (int i = 0; i < 8; i++)
                breg[i] =
                    bias4[(size_t)(i * Pc + p0 + srow) * (Pc / 4) + (kqn >> 2) + sd4];
        }
        barC(s);

        // ---- passA: talking-heads mix + bias (in place), track max ----
        float mt = m_run;
        {
            float* trow = &bs[(h * 32 + lane) * 33];
#pragma unroll 4
            for (int kq = 0; kq < 32; kq++) {
                float tv = trow[kq];
#pragma unroll
                for (int hh = 0; hh < 8; hh++)
                    tv = fmaf(wv[hh], sm.SP[s][hh][kq][lane], tv);
                trow[kq] = tv;
                mt = fmaxf(mt, tv);
            }
        }
        float sc = __expf(m_run - mt);
        m_run = mt;
        l_run *= sc;
        {
            U64F2 sc2 = pk2(sc);
#pragma unroll
            for (int j = 0; j < 16; j++) o[j] = f2mul(o[j], sc2);
        }

        // ---- fused exp + P@V ----
        {
            const float* trow = &bs[(h * 32 + lane) * 33];
            const float4* vb = (const float4*)&sm.Vs[s][h][0][0];
#pragma unroll 2
            for (int kq = 0; kq < 32; kq++) {
                float e = __expf(trow[kq] - mt);
                l_run += e;
                U64F2 pr2 = pk2(e);
                const float4* vp = vb + (kq << 3);
#pragma unroll
                for (int j = 0; j < 8; j++) {
                    float4 vv = vp[j];
                    U64F2 vlo, vhi;
                    vlo.f = make_float2(vv.x, vv.y);
                    vhi.f = make_float2(vv.z, vv.w);
                    o[2 * j]     = f2fma(pr2, vlo, o[2 * j]);
                    o[2 * j + 1] = f2fma(pr2, vhi, o[2 * j + 1]);
                }
            }
        }
        barC(s);  // protect Ks/Vs/SP for next tile
    }

    // ---- merge the two copies ----
    __syncthreads();
    if (s == 1) {
        sm.ml1[h][lane][0] = m_run;
        sm.ml1[h][lane][1] = l_run;
        float* ob = &sm.Ks[1][h][lane][0];  // copy-1 K area as o-buffer (stride 36)
#pragma unroll
        for (int i = 0; i < 8; i++) {
            float4 v;
            v.x = o[2 * i].f.x;     v.y = o[2 * i].f.y;
            v.z = o[2 * i + 1].f.x; v.w = o[2 * i + 1].f.y;
            *(float4*)&ob[i << 2] = v;
        }
    }
    __syncthreads();
    if (s == 0) {
        float m1 = sm.ml1[h][lane][0], l1 = sm.ml1[h][lane][1];
        float m = fmaxf(m_run, m1);
        float e0 = __expf(m_run - m), e1 = __expf(m1 - m);
        float linv = 1.0f / (l_run * e0 + l1 * e1);
        const float* ob = &sm.Ks[1][h][lane][0];
        float* outp = &g_ctxt[((size_t)(b * Pc + p0 + lane) * (Hc * DFc)) + h * DFc];
        U64F2 c0 = pk2(e0 * linv), c1 = pk2(e1 * linv);
#pragma unroll
        for (int i = 0; i < 8; i++) {
            float4 o1v = *(const float4*)&ob[i << 2];
            U64F2 lo, hi, b0, b1;
            b0.f = make_float2(o1v.x, o1v.y);
            b1.f = make_float2(o1v.z, o1v.w);
            lo = f2fma(c1, b0, f2mul(o[2 * i], c0));
            hi = f2fma(c1, b1, f2mul(o[2 * i + 1], c0));
            float4 v;
            v.x = lo.f.x; v.y = lo.f.y; v.z = hi.f.x; v.w = hi.f.y;
            ((float4*)outp)[i] = v;
        }
    }
}

// ---------------------------------------------------------------------------
extern "C" void kernel_launch(void* const* d_in, const int* in_sizes, int n_in,
                              void* d_out, int out_size) {
    (void)in_sizes; (void)n_in; (void)out_size;
    const float* x     = (const float*)d_in[0];
    const float* bias  = (const float*)d_in[1];
    const float* wqkv  = (const float*)d_in[2];
    const float* wtalk = (const float*)d_in[3];
    const float* wproj = (const float*)d_in[4];
    float* out = (float*)d_out;

    cudaFuncSetAttribute(attn_fused, cudaFuncAttributeMaxDynamicSharedMemorySize,
                         (int)sizeof(AttnSmem));

    void* ctxt_ptr = nullptr;
    cudaGetSymbolAddress(&ctxt_ptr, g_ctxt);

    gemm_nt<1><<<dim3(64, 12), 256>>>(x, wqkv, nullptr, Bc * Pc, 3 * Hc * DFc, 128);

    attn_fused<<<(Pc / 32) * Bc, 512, sizeof(AttnSmem)>>>(bias, wtalk);

    gemm_nt<0><<<dim3(64, 2), 256>>>((const float*)ctxt_ptr, wproj, out,
                                     Bc * Pc, 128, Hc * DFc);
}

// round 8
// speedup vs baseline: 2.0034x; 2.0034x over previous
#include <cuda_runtime.h>
#include <cuda_bf16.h>
#include <cstdint>

#define DEV_INLINE __device__ __forceinline__

// ------------------------------- f32x2 helpers (GEMM kernels) -------------
struct U64F2 { union { unsigned long long u; float2 f; }; };
DEV_INLINE U64F2 f2fma(U64F2 a, U64F2 b, U64F2 c) {
    U64F2 d;
    asm("fma.rn.f32x2 %0, %1, %2, %3;" : "=l"(d.u) : "l"(a.u), "l"(b.u), "l"(c.u));
    return d;
}
DEV_INLINE U64F2 pk2(float v) {
    U64F2 d;
    asm("mov.b64 %0, {%1, %1};" : "=l"(d.u) : "f"(v));
    return d;
}

// ------------------------------- mma.sync helpers -------------------------
DEV_INLINE void mma16816(float* c, const uint32_t* a, const uint32_t* b) {
    asm volatile(
        "mma.sync.aligned.m16n8k16.row.col.f32.bf16.bf16.f32 "
        "{%0,%1,%2,%3}, {%4,%5,%6,%7}, {%8,%9}, {%0,%1,%2,%3};"
        : "+f"(c[0]), "+f"(c[1]), "+f"(c[2]), "+f"(c[3])
        : "r"(a[0]), "r"(a[1]), "r"(a[2]), "r"(a[3]), "r"(b[0]), "r"(b[1]));
}
DEV_INLINE uint32_t packbf(float lo, float hi) {  // low half = lo
    uint32_t r;
    asm("cvt.rn.bf16x2.f32 %0, %1, %2;" : "=r"(r) : "f"(hi), "f"(lo));
    return r;
}
DEV_INLINE float bfround(float x) {
    return __bfloat162float(__float2bfloat16(x));
}

// ------------------------------- problem constants ------------------------
constexpr int Bc = 2, Pc = 2048, Hc = 8, DFc = 32;
constexpr float QSCALE = 0.17677669529663687f;  // 1/sqrt(32)

__device__ __align__(16) __nv_bfloat16 g_qhat[Bc * Pc * 256];      // [b,p,256]
__device__ __align__(16) __nv_bfloat16 g_khat[Bc * 8 * Pc * 256];  // [b,g,q,256]
__device__ __align__(16) __nv_bfloat16 g_vthi[Bc * 8 * 32 * Pc];   // [b,g,d,q]
__device__ __align__(16) __nv_bfloat16 g_vtlo[Bc * 8 * 32 * Pc];
__device__ __align__(16) float g_ctxt[Bc * Pc * 256];

// ---------------------------------------------------------------------------
// GEMM: C = A[M,K] @ Bw[N,K]^T. EPI=1: QKV epilogue -> qhat/khat/vt split.
// ---------------------------------------------------------------------------
template <int EPI>
__global__ __launch_bounds__(256) void gemm_nt(const float* __restrict__ A,
                                               const float* __restrict__ Bw,
                                               float* __restrict__ C,
                                               int M, int N, int K,
                                               const float* __restrict__ wtalk) {
    __shared__ __align__(16) float As[64][68];
    __shared__ __align__(16) float Bs[64][68];

    const int tid = threadIdx.x;
    const int tx = tid & 15, ty = tid >> 4;
    const int m0 = blockIdx.x << 6, n0 = blockIdx.y << 6;
    const int bn = tid & 63;
    const int bk = (tid >> 6) << 4;

    U64F2 acc[4][2];
#pragma unroll
    for (int i = 0; i < 4; i++) {
        acc[i][0].f = make_float2(0.f, 0.f);
        acc[i][1].f = make_float2(0.f, 0.f);
    }

    for (int kc = 0; kc < K; kc += 64) {
#pragma unroll
        for (int i = 0; i < 4; i++) {
            int v = tid + (i << 8);
            int r = v >> 4, k4 = v & 15;
            *(float4*)&As[r][k4 << 2] =
                *(const float4*)&A[(size_t)(m0 + r) * K + kc + (k4 << 2)];
        }
#pragma unroll
        for (int c4 = 0; c4 < 4; c4++) {
            float4 bv = *(const float4*)&Bw[(size_t)(n0 + bn) * K + kc + bk + (c4 << 2)];
            Bs[bk + (c4 << 2) + 0][bn] = bv.x;
            Bs[bk + (c4 << 2) + 1][bn] = bv.y;
            Bs[bk + (c4 << 2) + 2][bn] = bv.z;
            Bs[bk + (c4 << 2) + 3][bn] = bv.w;
        }
        __syncthreads();
#pragma unroll 8
        for (int kk = 0; kk < 64; kk++) {
            float4 b01 = *(const float4*)&Bs[kk][tx << 2];
            U64F2 b0, b1;
            b0.f = make_float2(b01.x, b01.y);
            b1.f = make_float2(b01.z, b01.w);
#pragma unroll
            for (int i = 0; i < 4; i++) {
                U64F2 a2 = pk2(As[(ty << 2) + i][kk]);
                acc[i][0] = f2fma(a2, b0, acc[i][0]);
                acc[i][1] = f2fma(a2, b1, acc[i][1]);
            }
        }
        __syncthreads();
    }

    if (EPI == 0) {
#pragma unroll
        for (int i = 0; i < 4; i++) {
            float4 vout;
            vout.x = acc[i][0].f.x; vout.y = acc[i][0].f.y;
            vout.z = acc[i][1].f.x; vout.w = acc[i][1].f.y;
            *(float4*)&C[(size_t)(m0 + (ty << 2) + i) * N + n0 + (tx << 2)] = vout;
        }
    } else {
        float wt[8][8];
#pragma unroll
        for (int gg = 0; gg < 8; gg++)
#pragma unroll
            for (int hh = 0; hh < 8; hh++) wt[gg][hh] = __ldg(&wtalk[gg * 8 + hh]);
#pragma unroll
        for (int i = 0; i < 4; i++) {
            float vals[4] = {acc[i][0].f.x, acc[i][0].f.y, acc[i][1].f.x, acc[i][1].f.y};
            int r = m0 + (ty << 2) + i;
            int bb = r >> 11, p = r & 2047;
#pragma unroll
            for (int j = 0; j < 4; j++) {
                int c = n0 + (tx << 2) + j;
                int sgrp = c >> 8;            // 0=q 1=k 2=v
                int h = (c >> 5) & 7, d = c & 31;
                float val = vals[j];
                if (sgrp == 0) {
                    g_qhat[((size_t)(bb * Pc) + p) * 256 + c] =
                        __float2bfloat16(val * QSCALE);
                } else if (sgrp == 1) {
                    int cc = c & 255;
#pragma unroll
                    for (int gg = 0; gg < 8; gg++)
                        g_khat[(((size_t)(bb * 8 + gg) * Pc) + p) * 256 + cc] =
                            __float2bfloat16(wt[gg][h] * val);
                } else {
                    __nv_bfloat16 hi = __float2bfloat16(val);
                    float rest = val - __bfloat162float(hi);
                    size_t idx = ((size_t)(bb * 8 + h) * 32 + d) * Pc + p;
                    g_vthi[idx] = hi;
                    g_vtlo[idx] = __float2bfloat16(rest);
                }
            }
        }
    }
}

// ---------------------------------------------------------------------------
// mma.sync fused talking-heads attention.
// CTA = (b, g, 128-row p tile); 256 thr, 8 warps; warp w = rows 16w..16w+15.
// Key tiles of 64. S in registers; P->bf16 hi/lo in registers (FA2 layout).
// ---------------------------------------------------------------------------
constexpr int QS_OFF = 0;                       // [128][264] bf16 = 67584
constexpr int KS_OFF = 67584;                   // [64][264]  bf16 = 33792
constexpr int VH_OFF = KS_OFF + 33792;          // [32][72]   bf16 = 4608
constexpr int VL_OFF = VH_OFF + 4608;
constexpr int SM_ATTN = VL_OFF + 4608;          // 110592 bytes

__global__ __launch_bounds__(256, 2) void attn_mma(const float* __restrict__ bias) {
    extern __shared__ char smem[];

    const int tid = threadIdx.x;
    const int w = tid >> 5, lane = tid & 31;
    const int la = lane >> 2, lb = lane & 3;
    const int b = blockIdx.x & 1;
    const int g = (blockIdx.x >> 1) & 7;
    const int p0 = (blockIdx.x >> 4) << 7;

    const __nv_bfloat16* qhat_b = g_qhat + ((size_t)b * Pc + p0) * 256;
    const __nv_bfloat16* khat_b = g_khat + (size_t)(b * 8 + g) * Pc * 256;
    const __nv_bfloat16* vthi_b = g_vthi + (size_t)(b * 8 + g) * 32 * Pc;
    const __nv_bfloat16* vtlo_b = g_vtlo + (size_t)(b * 8 + g) * 32 * Pc;

    // ---- stage Qhat [128][256] -> smem rows padded to 264 bf16 ----
#pragma unroll
    for (int i = 0; i < 16; i++) {
        int lin = tid + (i << 8);
        int row = lin >> 5, c16 = lin & 31;
        *(uint4*)(smem + QS_OFF + row * 528 + c16 * 16) =
            *(const uint4*)(qhat_b + (size_t)row * 256 + c16 * 8);
    }

    float s[8][4];        // S / P fragments: 8 n8-tiles x 4
    float o[4][4];        // O fragments: 4 n8-tiles (32 d) x 4
#pragma unroll
    for (int nt = 0; nt < 4; nt++)
#pragma unroll
        for (int i = 0; i < 4; i++) o[nt][i] = 0.f;
    float mA = -1e30f, mB = -1e30f, lA = 0.f, lB = 0.f;

    const int grA = p0 + 16 * w + la;
    const float* biasA = bias + ((size_t)g * Pc + grA) * Pc;
    const float* biasB = biasA + 8 * Pc;

    for (int t = 0; t < 32; t++) {
        const int q0 = t * 64;
        __syncthreads();   // previous tile fully consumed

        // ---- stage Khat tile [64][256] + Vt hi/lo [32][64] ----
#pragma unroll
        for (int i = 0; i < 8; i++) {
            int lin = tid + (i << 8);
            int row = lin >> 5, c16 = lin & 31;
            *(uint4*)(smem + KS_OFF + row * 528 + c16 * 16) =
                *(const uint4*)(khat_b + (size_t)(q0 + row) * 256 + c16 * 8);
        }
        {
            int row = tid >> 3, c16 = tid & 7;
            *(uint4*)(smem + VH_OFF + row * 144 + c16 * 16) =
                *(const uint4*)(vthi_b + (size_t)row * Pc + q0 + c16 * 8);
            *(uint4*)(smem + VL_OFF + row * 144 + c16 * 16) =
                *(const uint4*)(vtlo_b + (size_t)row * Pc + q0 + c16 * 8);
        }

        // ---- bias prefetch (hidden under staging + mma) ----
        float2 bA[8], bB[8];
#pragma unroll
        for (int nt = 0; nt < 8; nt++) {
            int q = q0 + 8 * nt + 2 * lb;
            bA[nt] = *(const float2*)(biasA + q);
            bB[nt] = *(const float2*)(biasB + q);
        }

#pragma unroll
        for (int nt = 0; nt < 8; nt++)
#pragma unroll
            for (int i = 0; i < 4; i++) s[nt][i] = 0.f;

        __syncthreads();   // staging visible

        // ---- QK~ MMA: S[16 x 64] over K=256 ----
        const char* qbase = smem + QS_OFF + (16 * w + la) * 528 + lb * 4;
        const char* kbase = smem + KS_OFF + la * 528 + lb * 4;
#pragma unroll
        for (int ks = 0; ks < 16; ks++) {
            uint32_t a[4];
            a[0] = *(const uint32_t*)(qbase + ks * 32);
            a[1] = *(const uint32_t*)(qbase + ks * 32 + 8 * 528);
            a[2] = *(const uint32_t*)(qbase + ks * 32 + 16);
            a[3] = *(const uint32_t*)(qbase + ks * 32 + 8 * 528 + 16);
#pragma unroll
            for (int nt = 0; nt < 8; nt++) {
                uint32_t bb[2];
                const char* kp = kbase + nt * 8 * 528 + ks * 32;
                bb[0] = *(const uint32_t*)(kp);
                bb[1] = *(const uint32_t*)(kp + 16);
                mma16816(s[nt], a, bb);
            }
        }

        // ---- bias add + online softmax (rows grA, grA+8) ----
        float mxA = mA, mxB = mB;
#pragma unroll
        for (int nt = 0; nt < 8; nt++) {
            s[nt][0] += bA[nt].x; s[nt][1] += bA[nt].y;
            s[nt][2] += bB[nt].x; s[nt][3] += bB[nt].y;
            mxA = fmaxf(mxA, fmaxf(s[nt][0], s[nt][1]));
            mxB = fmaxf(mxB, fmaxf(s[nt][2], s[nt][3]));
        }
        mxA = fmaxf(mxA, __shfl_xor_sync(0xffffffffu, mxA, 1));
        mxA = fmaxf(mxA, __shfl_xor_sync(0xffffffffu, mxA, 2));
        mxB = fmaxf(mxB, __shfl_xor_sync(0xffffffffu, mxB, 1));
        mxB = fmaxf(mxB, __shfl_xor_sync(0xffffffffu, mxB, 2));
        float scA = __expf(mA - mxA), scB = __expf(mB - mxB);
        mA = mxA; mB = mxB;
        float lsA = 0.f, lsB = 0.f;
#pragma unroll
        for (int nt = 0; nt < 8; nt++) {
            float e0 = __expf(s[nt][0] - mA), e1 = __expf(s[nt][1] - mA);
            float e2 = __expf(s[nt][2] - mB), e3 = __expf(s[nt][3] - mB);
            lsA += e0 + e1; lsB += e2 + e3;
            s[nt][0] = e0; s[nt][1] = e1; s[nt][2] = e2; s[nt][3] = e3;
        }
        lA = lA * scA + lsA;
        lB = lB * scB + lsB;
#pragma unroll
        for (int nt = 0; nt < 4; nt++) {
            o[nt][0] *= scA; o[nt][1] *= scA;
            o[nt][2] *= scB; o[nt][3] *= scB;
        }

        // ---- PV: O += (Phi+Plo) @ (Vhi+Vlo)  (3 passes, P from regs) ----
        // C-frag -> A-frag identity: a0 = c0c1(keys 16j..+7), a1 = c2c3(same),
        //                            a2 = c0c1(keys 16j+8..+15), a3 = c2c3(same)
        const char* vhb = smem + VH_OFF + la * 144 + lb * 4;
        const char* vlb = smem + VL_OFF + la * 144 + lb * 4;
#pragma unroll
        for (int j = 0; j < 4; j++) {
            uint32_t phi[4], plo[4];
            {
                const float* e0p = s[2 * j];      // keys 16j..16j+7
                const float* e1p = s[2 * j + 1];  // keys 16j+8..16j+15
                float h0 = bfround(e0p[0]), h1 = bfround(e0p[1]);
                float h2 = bfround(e0p[2]), h3 = bfround(e0p[3]);
                float g0 = bfround(e1p[0]), g1 = bfround(e1p[1]);
                float g2 = bfround(e1p[2]), g3 = bfround(e1p[3]);
                phi[0] = packbf(e0p[0], e0p[1]);   // rows la,   k-left
                phi[1] = packbf(e0p[2], e0p[3]);   // rows la+8, k-left
                phi[2] = packbf(e1p[0], e1p[1]);   // rows la,   k-right
                phi[3] = packbf(e1p[2], e1p[3]);   // rows la+8, k-right
                plo[0] = packbf(e0p[0] - h0, e0p[1] - h1);
                plo[1] = packbf(e0p[2] - h2, e0p[3] - h3);
                plo[2] = packbf(e1p[0] - g0, e1p[1] - g1);
                plo[3] = packbf(e1p[2] - g2, e1p[3] - g3);
            }
#pragma unroll
            for (int nt = 0; nt < 4; nt++) {
                const char* vh = vhb + nt * 8 * 144 + j * 32;
                const char* vl = vlb + nt * 8 * 144 + j * 32;
                uint32_t bh[2], blo[2];
                bh[0] = *(const uint32_t*)(vh);
                bh[1] = *(const uint32_t*)(vh + 16);
                blo[0] = *(const uint32_t*)(vl);
                blo[1] = *(const uint32_t*)(vl + 16);
                mma16816(o[nt], phi, bh);
                mma16816(o[nt], phi, blo);
                mma16816(o[nt], plo, bh);
            }
        }
    }

    // ---- epilogue: quad-reduce l, normalize, store ----
    lA += __shfl_xor_sync(0xffffffffu, lA, 1);
    lA += __shfl_xor_sync(0xffffffffu, lA, 2);
    lB += __shfl_xor_sync(0xffffffffu, lB, 1);
    lB += __shfl_xor_sync(0xffffffffu, lB, 2);
    float liA = 1.0f / lA, liB = 1.0f / lB;
    float* ctxtA = g_ctxt + ((size_t)b * Pc + grA) * 256 + g * 32 + 2 * lb;
    float* ctxtB = ctxtA + 8 * 256;
#pragma unroll
    for (int nt = 0; nt < 4; nt++) {
        *(float2*)(ctxtA + 8 * nt) = make_float2(o[nt][0] * liA, o[nt][1] * liA);
        *(float2*)(ctxtB + 8 * nt) = make_float2(o[nt][2] * liB, o[nt][3] * liB);
    }
}

// ---------------------------------------------------------------------------
extern "C" void kernel_launch(void* const* d_in, const int* in_sizes, int n_in,
                              void* d_out, int out_size) {
    (void)in_sizes; (void)n_in; (void)out_size;
    const float* x     = (const float*)d_in[0];
    const float* bias  = (const float*)d_in[1];
    const float* wqkv  = (const float*)d_in[2];
    const float* wtalk = (const float*)d_in[3];
    const float* wproj = (const float*)d_in[4];
    float* out = (float*)d_out;

    cudaFuncSetAttribute(attn_mma, cudaFuncAttributeMaxDynamicSharedMemorySize,
                         SM_ATTN);

    void* ctxt_ptr = nullptr;
    cudaGetSymbolAddress(&ctxt_ptr, g_ctxt);

    // 1) QKV projection + qhat/khat/vt-split epilogue
    gemm_nt<1><<<dim3(64, 12), 256>>>(x, wqkv, nullptr, Bc * Pc, 3 * Hc * DFc, 128,
                                      wtalk);

    // 2) mma.sync fused talking-heads attention -> g_ctxt
    attn_mma<<<16 * 8 * 2, 256, SM_ATTN>>>(bias);

    // 3) output projection
    gemm_nt<0><<<dim3(64, 2), 256>>>((const float*)ctxt_ptr, wproj, out,
                                     Bc * Pc, 128, Hc * DFc, nullptr);
}